// round 7
// baseline (speedup 1.0000x reference)
#include <cuda_runtime.h>
#include <cuda_bf16.h>
#include <math.h>

#define N_NODES  1000000
#define N_EDGES  16000000
#define N_GRAPHS 1024
#define SCAN_BLOCKS 977          // ceil(1e6 / 1024)

// ---------------- scratch (device globals: allocation-free) ----------------
__device__ __align__(16) float4 g_x1[2000000];     // x1: 1M x 8 fp32 (32 MB)
__device__ __align__(16) float4 g_x2[1000000];     // x2: 1M x 4 fp32 (16 MB)
__device__ __align__(16) int    g_deg_out[N_NODES];
__device__ __align__(16) int    g_deg_in[N_NODES];
__device__ __align__(16) int    g_offs[N_NODES];   // CSR row starts (by dst)
__device__ __align__(16) int    g_cursor[N_NODES]; // mutable copy for permute
__device__ int    g_blocksums[1024];
__device__ int    g_sorted_src[N_EDGES];           // src ids sorted by dst (64 MB)
__device__ float  g_gsum[N_GRAPHS * 4];
__device__ float  g_gcnt[N_GRAPHS];

// ---------------- kernels ----------------

// zero degrees + graph accumulators (nothing else needs zeroing anymore)
__global__ void k_zero() {
    int i = blockIdx.x * blockDim.x + threadIdx.x;
    if (i < N_NODES / 4) { ((int4*)g_deg_out)[i] = make_int4(0,0,0,0);
                           ((int4*)g_deg_in)[i]  = make_int4(0,0,0,0); }
    if (i < N_GRAPHS) { ((float4*)g_gsum)[i] = make_float4(0.f,0.f,0.f,0.f);
                        g_gcnt[i] = 0.f; }
}

// degrees: 4 edges per thread
__global__ void k_degrees(const int* __restrict__ src, const int* __restrict__ dst) {
    int i = blockIdx.x * blockDim.x + threadIdx.x;
    if (i >= N_EDGES / 4) return;
    int4 s = ((const int4*)src)[i];
    int4 d = ((const int4*)dst)[i];
    atomicAdd(&g_deg_out[s.x], 1); atomicAdd(&g_deg_out[s.y], 1);
    atomicAdd(&g_deg_out[s.z], 1); atomicAdd(&g_deg_out[s.w], 1);
    atomicAdd(&g_deg_in[d.x], 1);  atomicAdd(&g_deg_in[d.y], 1);
    atomicAdd(&g_deg_in[d.z], 1);  atomicAdd(&g_deg_in[d.w], 1);
}

// ---- exclusive scan of deg_in -> offs (3 kernels, 1024-element tiles) ----
__global__ void k_scanA() {
    __shared__ int sh[256];
    int bid = blockIdx.x, t = threadIdx.x;
    int base = bid * 1024 + t * 4;
    int4 v = make_int4(0,0,0,0);
    if (base + 3 < N_NODES) v = *(const int4*)&g_deg_in[base];
    else {
        if (base + 0 < N_NODES) v.x = g_deg_in[base + 0];
        if (base + 1 < N_NODES) v.y = g_deg_in[base + 1];
        if (base + 2 < N_NODES) v.z = g_deg_in[base + 2];
        if (base + 3 < N_NODES) v.w = g_deg_in[base + 3];
    }
    int s0 = v.x, s1 = s0 + v.y, s2 = s1 + v.z, s3 = s2 + v.w;
    sh[t] = s3;
    __syncthreads();
    // Hillis-Steele inclusive scan over 256 thread sums
    for (int off = 1; off < 256; off <<= 1) {
        int val = (t >= off) ? sh[t - off] : 0;
        __syncthreads();
        sh[t] += val;
        __syncthreads();
    }
    int excl = (t > 0) ? sh[t - 1] : 0;
    if (t == 255) g_blocksums[bid] = sh[255];
    int4 o = make_int4(excl, excl + s0, excl + s1, excl + s2);
    if (base + 3 < N_NODES) *(int4*)&g_offs[base] = o;
    else {
        if (base + 0 < N_NODES) g_offs[base + 0] = o.x;
        if (base + 1 < N_NODES) g_offs[base + 1] = o.y;
        if (base + 2 < N_NODES) g_offs[base + 2] = o.z;
        if (base + 3 < N_NODES) g_offs[base + 3] = o.w;
    }
}

__global__ void k_scanB() {
    __shared__ int sh[1024];
    int t = threadIdx.x;
    sh[t] = (t < SCAN_BLOCKS) ? g_blocksums[t] : 0;
    __syncthreads();
    for (int off = 1; off < 1024; off <<= 1) {
        int val = (t >= off) ? sh[t - off] : 0;
        __syncthreads();
        sh[t] += val;
        __syncthreads();
    }
    g_blocksums[t] = (t > 0) ? sh[t - 1] : 0;   // exclusive
}

__global__ void k_scanC() {
    int bid = blockIdx.x, t = threadIdx.x;
    int base = bid * 1024 + t * 4;
    int add = g_blocksums[bid];
    if (base + 3 < N_NODES) {
        int4 o = *(const int4*)&g_offs[base];
        o.x += add; o.y += add; o.z += add; o.w += add;
        *(int4*)&g_offs[base]   = o;
        *(int4*)&g_cursor[base] = o;
    } else {
        for (int k = 0; k < 4; k++)
            if (base + k < N_NODES) {
                int o = g_offs[base + k] + add;
                g_offs[base + k] = o; g_cursor[base + k] = o;
            }
    }
}

// counting-sort permute: sorted_src holds src ids grouped by dst
__global__ void k_permute(const int* __restrict__ src, const int* __restrict__ dst) {
    int i = blockIdx.x * blockDim.x + threadIdx.x;
    if (i >= N_EDGES / 4) return;
    int4 s = ((const int4*)src)[i];
    int4 d = ((const int4*)dst)[i];
    int p;
    p = atomicAdd(&g_cursor[d.x], 1); g_sorted_src[p] = s.x;
    p = atomicAdd(&g_cursor[d.y], 1); g_sorted_src[p] = s.y;
    p = atomicAdd(&g_cursor[d.z], 1); g_sorted_src[p] = s.z;
    p = atomicAdd(&g_cursor[d.w], 1); g_sorted_src[p] = s.w;
}

// x1 = (features * out_norm) @ W1
__global__ void k_proj1(const float* __restrict__ feat, const float* __restrict__ W1) {
    __shared__ float sW[80];
    if (threadIdx.x < 80) sW[threadIdx.x] = W1[threadIdx.x];
    __syncthreads();
    int n = blockIdx.x * blockDim.x + threadIdx.x;
    if (n >= N_NODES) return;
    float onorm = rsqrtf(fmaxf((float)g_deg_out[n], 1.f));
    const float2* fp = (const float2*)(feat + (size_t)n * 10);
    float f[10];
#pragma unroll
    for (int i = 0; i < 5; i++) { float2 v = fp[i]; f[2*i] = v.x * onorm; f[2*i+1] = v.y * onorm; }
    float o[8];
#pragma unroll
    for (int j = 0; j < 8; j++) o[j] = 0.f;
#pragma unroll
    for (int i = 0; i < 10; i++)
#pragma unroll
        for (int j = 0; j < 8; j++) o[j] += f[i] * sW[i * 8 + j];
    g_x1[n * 2]     = make_float4(o[0], o[1], o[2], o[3]);
    g_x1[n * 2 + 1] = make_float4(o[4], o[5], o[6], o[7]);
}

// gather layer 1, fused: agg = sum x1[src]; h1 = relu(agg*innorm+b1);
// x2 = (h1*onorm) @ W2  -- no atomics, no intermediate agg buffer
__global__ void k_gather1(const float* __restrict__ W2, const float* __restrict__ b1) {
    __shared__ float sW[32], sb[8];
    if (threadIdx.x < 32) sW[threadIdx.x] = W2[threadIdx.x];
    if (threadIdx.x < 8)  sb[threadIdx.x] = b1[threadIdx.x];
    __syncthreads();
    int n = blockIdx.x * blockDim.x + threadIdx.x;
    if (n >= N_NODES) return;
    int start = g_offs[n];
    int cnt   = g_deg_in[n];
    float4 a0 = make_float4(0.f,0.f,0.f,0.f), a1 = a0;
    for (int i = 0; i < cnt; i++) {
        int s = __ldg(g_sorted_src + start + i);
        float4 v0 = __ldg(&g_x1[2 * s]);
        float4 v1 = __ldg(&g_x1[2 * s + 1]);
        a0.x += v0.x; a0.y += v0.y; a0.z += v0.z; a0.w += v0.w;
        a1.x += v1.x; a1.y += v1.y; a1.z += v1.z; a1.w += v1.w;
    }
    float innorm = rsqrtf(fmaxf((float)cnt, 1.f));
    float onorm  = rsqrtf(fmaxf((float)g_deg_out[n], 1.f));
    float h[8] = { a0.x, a0.y, a0.z, a0.w, a1.x, a1.y, a1.z, a1.w };
#pragma unroll
    for (int j = 0; j < 8; j++) h[j] = fmaxf(h[j] * innorm + sb[j], 0.f);
    float o[4] = {0.f, 0.f, 0.f, 0.f};
#pragma unroll
    for (int j = 0; j < 8; j++)
#pragma unroll
        for (int k = 0; k < 4; k++) o[k] += h[j] * sW[j * 4 + k];
    g_x2[n] = make_float4(o[0] * onorm, o[1] * onorm, o[2] * onorm, o[3] * onorm);
}

// gather layer 2, fused with graph mean accumulation (graph_ids sorted ->
// warps are almost always gid-uniform: shuffle-reduce then 5 atomics/warp)
__global__ void k_gather2(const int* __restrict__ graph_ids, const float* __restrict__ b2) {
    int n0 = blockIdx.x * blockDim.x + threadIdx.x;
    bool valid = (n0 < N_NODES);
    int n = valid ? n0 : (N_NODES - 1);
    int start = g_offs[n];
    int cnt   = valid ? g_deg_in[n] : 0;
    float4 a = make_float4(0.f,0.f,0.f,0.f);
    for (int i = 0; i < cnt; i++) {
        int s = __ldg(g_sorted_src + start + i);
        float4 v = __ldg(&g_x2[s]);
        a.x += v.x; a.y += v.y; a.z += v.z; a.w += v.w;
    }
    float innorm = rsqrtf(fmaxf((float)g_deg_in[n], 1.f));
    float h[4];
    h[0] = valid ? fmaxf(a.x * innorm + __ldg(b2 + 0), 0.f) : 0.f;
    h[1] = valid ? fmaxf(a.y * innorm + __ldg(b2 + 1), 0.f) : 0.f;
    h[2] = valid ? fmaxf(a.z * innorm + __ldg(b2 + 2), 0.f) : 0.f;
    h[3] = valid ? fmaxf(a.w * innorm + __ldg(b2 + 3), 0.f) : 0.f;
    float cntf = valid ? 1.f : 0.f;
    int gid = __ldg(graph_ids + n);

    unsigned full = 0xFFFFFFFFu;
    int g0 = __shfl_sync(full, gid, 0);
    bool uniform = __all_sync(full, gid == g0);
    int lane = threadIdx.x & 31;
    if (uniform) {
#pragma unroll
        for (int off = 16; off > 0; off >>= 1) {
#pragma unroll
            for (int k = 0; k < 4; k++) h[k] += __shfl_down_sync(full, h[k], off);
            cntf += __shfl_down_sync(full, cntf, off);
        }
        if (lane == 0) {
#pragma unroll
            for (int k = 0; k < 4; k++) atomicAdd(&g_gsum[g0 * 4 + k], h[k]);
            atomicAdd(&g_gcnt[g0], cntf);
        }
    } else if (valid) {
#pragma unroll
        for (int k = 0; k < 4; k++) atomicAdd(&g_gsum[gid * 4 + k], h[k]);
        atomicAdd(&g_gcnt[gid], 1.f);
    }
}

// out[g] = sigmoid(mean @ Wo + bo)
__global__ void k_final(const float* __restrict__ Wo, const float* __restrict__ bo,
                        float* __restrict__ out) {
    int g = blockIdx.x * blockDim.x + threadIdx.x;
    if (g >= N_GRAPHS) return;
    float c = fmaxf(g_gcnt[g], 1.f);
    float z = __ldg(bo);
#pragma unroll
    for (int k = 0; k < 4; k++) z += (g_gsum[g * 4 + k] / c) * __ldg(Wo + k);
    out[g] = 1.f / (1.f + expf(-z));
}

// ---------------- launch ----------------
extern "C" void kernel_launch(void* const* d_in, const int* in_sizes, int n_in,
                              void* d_out, int out_size) {
    const float* feat      = (const float*)d_in[0];
    const int*   src       = (const int*)d_in[1];
    const int*   dst       = (const int*)d_in[2];
    const int*   graph_ids = (const int*)d_in[3];
    const float* W1        = (const float*)d_in[4];
    const float* b1        = (const float*)d_in[5];
    const float* W2        = (const float*)d_in[6];
    const float* b2        = (const float*)d_in[7];
    const float* Wo        = (const float*)d_in[8];
    const float* bo        = (const float*)d_in[9];
    float* out = (float*)d_out;

    const int T = 256;
    k_zero<<<(N_NODES / 4 + T - 1) / T, T>>>();
    k_degrees<<<((N_EDGES / 4) + T - 1) / T, T>>>(src, dst);
    k_scanA<<<SCAN_BLOCKS, 256>>>();
    k_scanB<<<1, 1024>>>();
    k_scanC<<<SCAN_BLOCKS, 256>>>();
    k_permute<<<((N_EDGES / 4) + T - 1) / T, T>>>(src, dst);
    k_proj1<<<(N_NODES + T - 1) / T, T>>>(feat, W1);
    k_gather1<<<(N_NODES + T - 1) / T, T>>>(W2, b1);
    k_gather2<<<(N_NODES + T - 1) / T, T>>>(graph_ids, b2);
    k_final<<<(N_GRAPHS + T - 1) / T, T>>>(Wo, bo, out);
}